// round 4
// baseline (speedup 1.0000x reference)
#include <cuda_runtime.h>
#include <cuda_bf16.h>

// Fused gamma-pdf-weighted MSE mean reduction — single kernel, last-block-done.
// mean( 0.5*(output-target)^2 * ef(target) )
// ef(y) = (BETA - c)*(1 - pdf(y)/FX_MAX) + c,  c = 1/(Y_MAX - Y_MIN)
//
// pdf/FX_MAX = exp( (a-1)*ln(x) - x + C0 ). For fp32 uniform targets this is
// < 4e-19 except at exact zeros, so log/exp runs only in a cold branch
// (y < 1e-6) — the hot loop has no MUFU.
//
// R4: MLP tuning. R3 measured DRAM=61% @ occ 94%, regs=30 -> only ~2 LDG.128
// in flight per thread (latency-exposed). Now: unroll-by-4 (8 batched LDG.128
// per thread), 5 blocks/SM (51-reg budget, 40 warps/SM) -> 40KB in flight/SM,
// well past the ~16KB Little's-law requirement for ~7TB/s.

#define NBLK 740    // 148 SMs * 5
#define NTH  256

__device__ float        g_part[NBLK];
__device__ unsigned int g_count;   // zero-init at module load; self-resetting

__device__ __forceinline__ float elem_val(float o, float y) {
    const float A1        = -0.9355570857535674f;            // EST_A - 1
    const float NEG_LOC   = 1.1328205299926424e-27f;         // -EST_LOC
    const float INV_SCALE = (float)(1.0 / 1.5376362609160314);
    const float C0        = -58.4492351f;                    // -lgamma(a)-ln(scale)-ln(FX_MAX)
    const float C         = (float)(1.0 / 107.2185);         // 1/(Y_MAX - Y_MIN)
    const float BC        = 5.0f - (float)(1.0 / 107.2185);  // BETA - c

    float r = 0.0f;
    if (y < 1e-6f) {                      // cold path: only (near-)zero targets
        float x  = (y + NEG_LOC) * INV_SCALE;
        float lp = fmaf(A1, __logf(x), C0) - x;
        r = __expf(lp);                   // = pdf/FX_MAX
    }
    float ef   = fmaf(BC, 1.0f - r, C);   // (BETA-c)*(1-r) + c
    float diff = o - y;
    return 0.5f * diff * diff * ef;
}

__device__ __forceinline__ float quad_val(float4 o, float4 t) {
    return elem_val(o.x, t.x) + elem_val(o.y, t.y)
         + elem_val(o.z, t.z) + elem_val(o.w, t.w);
}

__global__ __launch_bounds__(NTH, 5) void loss_fused_kernel(
    const float* __restrict__ out, const float* __restrict__ tgt,
    float* __restrict__ result, int n)
{
    const int tid    = threadIdx.x;
    const int lane   = tid & 31;
    const int warp   = tid >> 5;
    const int idx    = blockIdx.x * NTH + tid;
    const int stride = gridDim.x * NTH;
    const int n4     = n >> 2;

    const float4* __restrict__ o4 = (const float4*)out;
    const float4* __restrict__ t4 = (const float4*)tgt;

    float sum = 0.0f;
    int i = idx;

    // Unroll-by-4: issue all 8 LDG.128 before any compute (MLP=8/thread).
    for (; i + 3 * stride < n4; i += 4 * stride) {
        float4 o0 = o4[i];
        float4 t0 = t4[i];
        float4 o1 = o4[i + stride];
        float4 t1 = t4[i + stride];
        float4 o2 = o4[i + 2 * stride];
        float4 t2 = t4[i + 2 * stride];
        float4 o3 = o4[i + 3 * stride];
        float4 t3 = t4[i + 3 * stride];
        sum += quad_val(o0, t0);
        sum += quad_val(o1, t1);
        sum += quad_val(o2, t2);
        sum += quad_val(o3, t3);
    }
    for (; i < n4; i += stride)           // float4 remainder
        sum += quad_val(o4[i], t4[i]);
    for (int j = (n4 << 2) + idx; j < n; j += stride)   // scalar tail
        sum += elem_val(out[j], tgt[j]);

    // ---- block reduce (all shuffles in fully-active warps) ----
    #pragma unroll
    for (int off = 16; off > 0; off >>= 1)
        sum += __shfl_down_sync(0xFFFFFFFFu, sum, off);

    __shared__ float s_warp[NTH / 32];
    __shared__ bool  s_last;
    if (lane == 0) s_warp[warp] = sum;
    __syncthreads();

    if (warp == 0) {                      // full warp active
        float v = (lane < NTH / 32) ? s_warp[lane] : 0.0f;
        #pragma unroll
        for (int off = 16; off > 0; off >>= 1)
            v += __shfl_down_sync(0xFFFFFFFFu, v, off);
        if (lane == 0) {
            g_part[blockIdx.x] = v;
            __threadfence();                              // release partial
            unsigned int prev = atomicInc(&g_count, NBLK - 1u);  // wraps->0 on last
            s_last = (prev == NBLK - 1u);
        }
    }
    __syncthreads();

    if (s_last) {
        __threadfence();                  // acquire before reading g_part
        double acc = 0.0;                 // fixed-order deterministic reduce
        for (int k = tid; k < NBLK; k += NTH)
            acc += (double)g_part[k];

        #pragma unroll
        for (int off = 16; off > 0; off >>= 1)
            acc += __shfl_down_sync(0xFFFFFFFFu, acc, off);

        __shared__ double s_d[NTH / 32];
        if (lane == 0) s_d[warp] = acc;
        __syncthreads();

        if (warp == 0) {                  // full warp active
            double v = (lane < NTH / 32) ? s_d[lane] : 0.0;
            #pragma unroll
            for (int off = 16; off > 0; off >>= 1)
                v += __shfl_down_sync(0xFFFFFFFFu, v, off);
            if (lane == 0)
                result[0] = (float)(v / (double)n);
        }
    }
}

extern "C" void kernel_launch(void* const* d_in, const int* in_sizes, int n_in,
                              void* d_out, int out_size)
{
    const float* output = (const float*)d_in[0];
    const float* target = (const float*)d_in[1];
    const int n = in_sizes[0];

    loss_fused_kernel<<<NBLK, NTH>>>(output, target, (float*)d_out, n);
}